// round 11
// baseline (speedup 1.0000x reference)
#include <cuda_runtime.h>
#include <cuda_fp16.h>
#include <cstdint>
#include <cstddef>

#define BATCH 16384
#define HDIM  512
#define ODIM  128
#define NEXP  5
#define NZ    15

#define BM    128
#define BK    64             // halfs per k-tile (128B rows)
#define NKT   (HDIM/BK)      // 8
#define STAGES 3

// gemm1 config: BN=64, 128 thr, 3 CTAs/SM, frag double-buffer
#define BN1   64
#define STG1  24576          // 16KB A + 8KB B
// gemm2 config (R10): BN=128, 128 thr, warp 64x64
#define BN2   128
#define STG2  32768
#define B_OFF2 16384

// device scratch (static; allocation-guard-safe)
__device__ __half g_Xh [(size_t)3  * BATCH * HDIM];
__device__ __half g_H  [(size_t)NZ * BATCH * HDIM];
__device__ __half g_W1h[(size_t)NZ * HDIM * HDIM];    // [z][n][k]
__device__ __half g_W2h[(size_t)NZ * ODIM * HDIM];    // [z][n][k]

// ---------------------------------------------------------------------------
// helpers
// ---------------------------------------------------------------------------
__device__ __forceinline__ uint32_t smem_u32(const void* p) {
    uint32_t a;
    asm("{ .reg .u64 t; cvta.to.shared.u64 t, %1; cvt.u32.u64 %0, t; }" : "=r"(a) : "l"(p));
    return a;
}
__device__ __forceinline__ void cp16(uint32_t s, const void* g) {
    asm volatile("cp.async.cg.shared.global [%0], [%1], 16;\n" :: "r"(s), "l"(g));
}
__device__ __forceinline__ void cp_commit() { asm volatile("cp.async.commit_group;\n"); }
template<int N> __device__ __forceinline__ void cp_wait() {
    asm volatile("cp.async.wait_group %0;\n" :: "n"(N));
}
__device__ __forceinline__ void ldsm4(uint32_t& d0, uint32_t& d1, uint32_t& d2, uint32_t& d3,
                                      uint32_t a) {
    asm volatile("ldmatrix.sync.aligned.m8n8.x4.shared.b16 {%0,%1,%2,%3}, [%4];"
                 : "=r"(d0), "=r"(d1), "=r"(d2), "=r"(d3) : "r"(a));
}
__device__ __forceinline__ void mma16816(float& d0, float& d1, float& d2, float& d3,
                                         uint32_t a0, uint32_t a1, uint32_t a2, uint32_t a3,
                                         uint32_t b0, uint32_t b1) {
    asm volatile(
        "mma.sync.aligned.m16n8k16.row.col.f32.f16.f16.f32 "
        "{%0,%1,%2,%3}, {%4,%5,%6,%7}, {%8,%9}, {%0,%1,%2,%3};"
        : "+f"(d0), "+f"(d1), "+f"(d2), "+f"(d3)
        : "r"(a0), "r"(a1), "r"(a2), "r"(a3), "r"(b0), "r"(b1));
}

// ---------------------------------------------------------------------------
// conversion kernels (validated; rel_err 4.1e-4)
// ---------------------------------------------------------------------------
__global__ void cvt_x_kernel(const float* __restrict__ x0, const float* __restrict__ x1,
                             const float* __restrict__ x2)
{
    const size_t per = (size_t)BATCH * HDIM / 4;
    const size_t i = (size_t)blockIdx.x * blockDim.x + threadIdx.x;
    if (i >= 3 * per) return;
    const int bank = (int)(i / per);
    const size_t r = i - (size_t)bank * per;
    const float4 v = ((const float4*)(bank == 0 ? x0 : bank == 1 ? x1 : x2))[r];
    __half2 h0 = __floats2half2_rn(v.x, v.y);
    __half2 h1 = __floats2half2_rn(v.z, v.w);
    ((uint2*)g_Xh)[i] = make_uint2(*(uint32_t*)&h0, *(uint32_t*)&h1);
}

__global__ void cvt_w_kernel(const float* __restrict__ sW1, const float* __restrict__ tW1,
                             const float* __restrict__ sW2, const float* __restrict__ tW2)
{
    __shared__ float t[32][33];
    int b = blockIdx.x;
    const float* src; __half* dst; int N, n0, k0;
    if (b < NZ * 256) {
        const int z = b >> 8, r = b & 255;
        n0 = (r >> 4) * 32; k0 = (r & 15) * 32;
        src = (z < NEXP) ? sW1 + (size_t)z * HDIM * HDIM
                         : tW1 + (size_t)(z - NEXP) * HDIM * HDIM;
        dst = g_W1h + (size_t)z * HDIM * HDIM;
        N = HDIM;
    } else {
        b -= NZ * 256;
        const int z = b >> 6, r = b & 63;
        k0 = (r >> 2) * 32; n0 = (r & 3) * 32;
        src = (z < NEXP) ? sW2 + (size_t)z * HDIM * ODIM
                         : tW2 + (size_t)(z - NEXP) * HDIM * ODIM;
        dst = g_W2h + (size_t)z * ODIM * HDIM;
        N = ODIM;
    }
    const int tx = threadIdx.x, ty = threadIdx.y;
    #pragma unroll
    for (int i = 0; i < 4; ++i)
        t[ty + i * 8][tx] = src[(size_t)(k0 + ty + i * 8) * N + n0 + tx];
    __syncthreads();
    #pragma unroll
    for (int i = 0; i < 4; ++i)
        dst[(size_t)(n0 + ty + i * 8) * HDIM + k0 + tx] = __float2half_rn(t[tx][ty + i * 8]);
}

// ---------------------------------------------------------------------------
// gemm1: BM=128 x BN1=64 tile, 4 warps (warp 64x32), 3 CTAs/SM,
// register fragment double-buffer: ldsm for k16+1 issued before MMAs of k16.
// ---------------------------------------------------------------------------
__global__ __launch_bounds__(128, 3)
void gemm1_kernel(const float* __restrict__ sb1, const float* __restrict__ tb1)
{
    __shared__ __align__(1024) char smem[STAGES * STG1];   // 72 KB
    const uint32_t sb = smem_u32(smem);

    const int tid = threadIdx.x, lane = tid & 31, wid = tid >> 5;
    const int wm = wid >> 1, wn = wid & 1;                  // 2m x 2n warps
    const int bn = blockIdx.x * BN1, bm = blockIdx.y * BM;
    const int z = blockIdx.z, bank = z / NEXP, e = z - bank * NEXP;

    const char* Ab = (const char*)(g_Xh + (size_t)bank * BATCH * HDIM);
    const char* Wb = (const char*)(g_W1h + (size_t)z * HDIM * HDIM);
    const float* bias = (bank == 0) ? sb1 + (size_t)e * HDIM
                                    : tb1 + ((size_t)(bank - 1) * NEXP + e) * HDIM;
    __half* Hc = g_H + (size_t)z * BATCH * HDIM;

    // cp.async mapping: A 8 granules/thread, B 4 granules/thread
    uint32_t aog[8], sAo[8];
    #pragma unroll
    for (int i = 0; i < 8; ++i) {
        const int idx = i * 128 + tid;
        const int r = idx >> 3, c = idx & 7;
        aog[i] = (uint32_t)(((bm + r) * HDIM + c * 8) * 2);
        sAo[i] = (uint32_t)(r * 128 + ((c ^ (r & 7)) << 4));
    }
    uint32_t bog[4], sBo[4];
    #pragma unroll
    for (int i = 0; i < 4; ++i) {
        const int idx = i * 128 + tid;
        const int r = idx >> 3, c = idx & 7;
        bog[i] = (uint32_t)(((bn + r) * HDIM + c * 8) * 2);
        sBo[i] = (uint32_t)(16384 + r * 128 + ((c ^ (r & 7)) << 4));
    }

    // fragment tables
    const int ah = lane >> 4;
    uint32_t art[4]; int arx[4];
    #pragma unroll
    for (int mi = 0; mi < 4; ++mi) {
        const int r = wm * 64 + mi * 16 + (lane & 15);
        art[mi] = (uint32_t)(r * 128); arx[mi] = r & 7;
    }
    const int bh = (lane >> 3) & 1;
    uint32_t nrt[2]; int nrx[2];
    #pragma unroll
    for (int p = 0; p < 2; ++p) {
        const int r = wn * 32 + p * 16 + ((lane >> 4) << 3) + (lane & 7);
        nrt[p] = (uint32_t)(16384 + r * 128); nrx[p] = r & 7;
    }

    float acc[4][4][4] = {};

    // prologue: 2 stages
    #pragma unroll
    for (int s = 0; s < STAGES - 1; ++s) {
        const uint32_t base = sb + s * STG1;
        const int ko = s * 128;     // bytes per k-chunk
        #pragma unroll
        for (int i = 0; i < 8; ++i) cp16(base + sAo[i], Ab + aog[i] + ko);
        #pragma unroll
        for (int i = 0; i < 4; ++i) cp16(base + sBo[i], Wb + bog[i] + ko);
        cp_commit();
    }

    uint32_t af[2][4][4], bf[2][4][2];

    #pragma unroll 1
    for (int kt = 0; kt < NKT; ++kt) {
        cp_wait<STAGES - 2>();
        __syncthreads();

        if (kt + STAGES - 1 < NKT) {
            const uint32_t base = sb + ((kt + STAGES - 1) % STAGES) * STG1;
            const int ko = (kt + STAGES - 1) * 128;
            #pragma unroll
            for (int i = 0; i < 8; ++i) cp16(base + sAo[i], Ab + aog[i] + ko);
            #pragma unroll
            for (int i = 0; i < 4; ++i) cp16(base + sBo[i], Wb + bog[i] + ko);
        }
        cp_commit();

        const uint32_t stg = sb + (kt % STAGES) * STG1;

        // preload k16=0 fragments
        {
            const int ga = ah, gb = bh;
            #pragma unroll
            for (int mi = 0; mi < 4; ++mi)
                ldsm4(af[0][mi][0], af[0][mi][1], af[0][mi][2], af[0][mi][3],
                      stg + art[mi] + ((uint32_t)(ga ^ arx[mi]) << 4));
            #pragma unroll
            for (int p = 0; p < 2; ++p)
                ldsm4(bf[0][2 * p][0], bf[0][2 * p][1], bf[0][2 * p + 1][0], bf[0][2 * p + 1][1],
                      stg + nrt[p] + ((uint32_t)(gb ^ nrx[p]) << 4));
        }

        #pragma unroll
        for (int k16 = 0; k16 < 4; ++k16) {
            const int cur = k16 & 1;
            if (k16 < 3) {   // prefetch next k16 fragments into alternate buffer
                const int ga = (k16 + 1) * 2 + ah, gb = (k16 + 1) * 2 + bh;
                #pragma unroll
                for (int mi = 0; mi < 4; ++mi)
                    ldsm4(af[cur ^ 1][mi][0], af[cur ^ 1][mi][1],
                          af[cur ^ 1][mi][2], af[cur ^ 1][mi][3],
                          stg + art[mi] + ((uint32_t)(ga ^ arx[mi]) << 4));
                #pragma unroll
                for (int p = 0; p < 2; ++p)
                    ldsm4(bf[cur ^ 1][2 * p][0], bf[cur ^ 1][2 * p][1],
                          bf[cur ^ 1][2 * p + 1][0], bf[cur ^ 1][2 * p + 1][1],
                          stg + nrt[p] + ((uint32_t)(gb ^ nrx[p]) << 4));
            }
            #pragma unroll
            for (int mi = 0; mi < 4; ++mi)
                #pragma unroll
                for (int ni = 0; ni < 4; ++ni)
                    mma16816(acc[mi][ni][0], acc[mi][ni][1], acc[mi][ni][2], acc[mi][ni][3],
                             af[cur][mi][0], af[cur][mi][1], af[cur][mi][2], af[cur][mi][3],
                             bf[cur][ni][0], bf[cur][ni][1]);
        }
    }

    // epilogue: bias + relu, half2 stores
    const int g = lane >> 2, t = lane & 3;
    #pragma unroll
    for (int mi = 0; mi < 4; ++mi) {
        const int r0g = bm + wm * 64 + mi * 16 + g;
        const int r1g = r0g + 8;
        #pragma unroll
        for (int ni = 0; ni < 4; ++ni) {
            const int c0g = bn + wn * 32 + ni * 8 + t * 2;
            const float bv0 = bias[c0g], bv1 = bias[c0g + 1];
            const float v00 = fmaxf(acc[mi][ni][0] + bv0, 0.0f);
            const float v01 = fmaxf(acc[mi][ni][1] + bv1, 0.0f);
            const float v10 = fmaxf(acc[mi][ni][2] + bv0, 0.0f);
            const float v11 = fmaxf(acc[mi][ni][3] + bv1, 0.0f);
            *(__half2*)&Hc[(size_t)r0g * HDIM + c0g] = __floats2half2_rn(v00, v01);
            *(__half2*)&Hc[(size_t)r1g * HDIM + c0g] = __floats2half2_rn(v10, v11);
        }
    }
}

// ---------------------------------------------------------------------------
// gemm2: unchanged R10 config — BM=128 x BN2=128, 4 warps (warp 64x64)
// ---------------------------------------------------------------------------
__global__ __launch_bounds__(128, 2)
void gemm2_kernel(const float* __restrict__ sb2, const float* __restrict__ tb2,
                  float* __restrict__ out)
{
    __shared__ __align__(1024) char smem[STAGES * STG2];   // 96 KB
    const uint32_t sb = smem_u32(smem);

    const int tid = threadIdx.x, lane = tid & 31, wid = tid >> 5;
    const int wm = wid >> 1, wn = wid & 1;
    const int bm = blockIdx.y * BM, bn = blockIdx.x * BN2;
    const int z = blockIdx.z, bank = z / NEXP, e = z - bank * NEXP;

    const __half* A = g_H + (size_t)z * BATCH * HDIM;
    const __half* W = g_W2h + (size_t)z * ODIM * HDIM;
    const float* bias = (bank == 0) ? sb2 + (size_t)e * ODIM
                                    : tb2 + ((size_t)(bank - 1) * NEXP + e) * ODIM;
    float* Cb = out + (size_t)z * BATCH * ODIM;

    const __half* Ag[8]; const __half* Bg[8]; uint32_t sAo[8], sBo[8];
    #pragma unroll
    for (int i = 0; i < 8; ++i) {
        const int idx = i * 128 + tid;
        const int r = idx >> 3, c = idx & 7;
        Ag[i] = A + (size_t)(bm + r) * HDIM + c * 8;
        Bg[i] = W + (size_t)(bn + r) * HDIM + c * 8;
        const uint32_t o = (uint32_t)(r * 128 + ((c ^ (r & 7)) << 4));
        sAo[i] = o;
        sBo[i] = B_OFF2 + o;
    }

    const int ah = lane >> 4;
    uint32_t art[4]; int arx[4];
    #pragma unroll
    for (int mi = 0; mi < 4; ++mi) {
        const int r = wm * 64 + mi * 16 + (lane & 15);
        art[mi] = (uint32_t)(r * 128); arx[mi] = r & 7;
    }
    const int bh = (lane >> 3) & 1;
    uint32_t nrt[4]; int nrx[4];
    #pragma unroll
    for (int p = 0; p < 4; ++p) {
        const int r = wn * 64 + p * 16 + ((lane >> 4) << 3) + (lane & 7);
        nrt[p] = B_OFF2 + (uint32_t)(r * 128); nrx[p] = r & 7;
    }

    float acc[4][8][4] = {};

    #pragma unroll
    for (int s = 0; s < STAGES - 1; ++s) {
        const int ko = s * BK;
        const uint32_t base = sb + s * STG2;
        #pragma unroll
        for (int i = 0; i < 8; ++i) { cp16(base + sAo[i], Ag[i] + ko); }
        #pragma unroll
        for (int i = 0; i < 8; ++i) { cp16(base + sBo[i], Bg[i] + ko); }
        cp_commit();
    }

    #pragma unroll 1
    for (int kt = 0; kt < NKT; ++kt) {
        cp_wait<STAGES - 2>();
        __syncthreads();

        if (kt + STAGES - 1 < NKT) {
            const int ko = (kt + STAGES - 1) * BK;
            const uint32_t base = sb + ((kt + STAGES - 1) % STAGES) * STG2;
            #pragma unroll
            for (int i = 0; i < 8; ++i) { cp16(base + sAo[i], Ag[i] + ko); }
            #pragma unroll
            for (int i = 0; i < 8; ++i) { cp16(base + sBo[i], Bg[i] + ko); }
        }
        cp_commit();

        const uint32_t stg = sb + (kt % STAGES) * STG2;
        #pragma unroll
        for (int k16 = 0; k16 < 4; ++k16) {
            const int ga = k16 * 2 + ah;
            const int gb = k16 * 2 + bh;
            uint32_t af[4][4], bf[8][2];
            #pragma unroll
            for (int mi = 0; mi < 4; ++mi)
                ldsm4(af[mi][0], af[mi][1], af[mi][2], af[mi][3],
                      stg + art[mi] + ((uint32_t)(ga ^ arx[mi]) << 4));
            #pragma unroll
            for (int p = 0; p < 4; ++p)
                ldsm4(bf[2 * p][0], bf[2 * p][1], bf[2 * p + 1][0], bf[2 * p + 1][1],
                      stg + nrt[p] + ((uint32_t)(gb ^ nrx[p]) << 4));
            #pragma unroll
            for (int mi = 0; mi < 4; ++mi)
                #pragma unroll
                for (int ni = 0; ni < 8; ++ni)
                    mma16816(acc[mi][ni][0], acc[mi][ni][1], acc[mi][ni][2], acc[mi][ni][3],
                             af[mi][0], af[mi][1], af[mi][2], af[mi][3],
                             bf[ni][0], bf[ni][1]);
        }
    }

    const int g = lane >> 2, t = lane & 3;
    #pragma unroll
    for (int mi = 0; mi < 4; ++mi) {
        const int r0g = bm + wm * 64 + mi * 16 + g;
        const int r1g = r0g + 8;
        #pragma unroll
        for (int ni = 0; ni < 8; ++ni) {
            const int c0g = bn + wn * 64 + ni * 8 + t * 2;
            const float bv0 = bias[c0g], bv1 = bias[c0g + 1];
            *(float2*)&Cb[(size_t)r0g * ODIM + c0g] =
                make_float2(acc[mi][ni][0] + bv0, acc[mi][ni][1] + bv1);
            *(float2*)&Cb[(size_t)r1g * ODIM + c0g] =
                make_float2(acc[mi][ni][2] + bv0, acc[mi][ni][3] + bv1);
        }
    }
}

// ---------------------------------------------------------------------------
// launch
// ---------------------------------------------------------------------------
extern "C" void kernel_launch(void* const* d_in, const int* in_sizes, int n_in,
                              void* d_out, int out_size)
{
    const float* share_x  = (const float*)d_in[0];
    const float* task_x0  = (const float*)d_in[1];
    const float* task_x1  = (const float*)d_in[2];
    const float* share_W1 = (const float*)d_in[3];
    const float* share_b1 = (const float*)d_in[4];
    const float* share_W2 = (const float*)d_in[5];
    const float* share_b2 = (const float*)d_in[6];
    const float* task_W1  = (const float*)d_in[7];
    const float* task_b1  = (const float*)d_in[8];
    const float* task_W2  = (const float*)d_in[9];
    const float* task_b2  = (const float*)d_in[10];
    float* out = (float*)d_out;

    const size_t nx4 = (size_t)3 * BATCH * HDIM / 4;
    cvt_x_kernel<<<(unsigned)((nx4 + 255) / 256), 256>>>(share_x, task_x0, task_x1);
    cvt_w_kernel<<<NZ * 256 + NZ * 64, dim3(32, 8)>>>(share_W1, task_W1, share_W2, task_W2);

    gemm1_kernel<<<dim3(HDIM / BN1, BATCH / BM, NZ), 128>>>(share_b1, task_b1);
    gemm2_kernel<<<dim3(ODIM / BN2, BATCH / BM, NZ), 128>>>(share_b2, task_b2, out);
}

// round 12
// speedup vs baseline: 1.4768x; 1.4768x over previous
#include <cuda_runtime.h>
#include <cuda_fp16.h>
#include <cstdint>
#include <cstddef>

#define BATCH 16384
#define HDIM  512
#define ODIM  128
#define NEXP  5
#define NZ    15

#define BM    128
#define BK    64             // halfs per k-tile (128B rows)
#define NKT   (HDIM/BK)      // 8
#define STAGES 3

// gemm1 (R10, best): BN=128, 128 thr, warp 64x64, 2 CTAs/SM
#define BN1   128
#define STG1  32768
#define B_OFF1 16384
// gemm2 (new): BN=64, 128 thr, warp 64x32, 3 CTAs/SM
#define BN2   64
#define STG2  24576          // 16KB A + 8KB B
#define B_OFF2 16384

// device scratch (static; allocation-guard-safe)
__device__ __half g_Xh [(size_t)3  * BATCH * HDIM];
__device__ __half g_H  [(size_t)NZ * BATCH * HDIM];
__device__ __half g_W1h[(size_t)NZ * HDIM * HDIM];    // [z][n][k]
__device__ __half g_W2h[(size_t)NZ * ODIM * HDIM];    // [z][n][k]

// ---------------------------------------------------------------------------
// helpers
// ---------------------------------------------------------------------------
__device__ __forceinline__ uint32_t smem_u32(const void* p) {
    uint32_t a;
    asm("{ .reg .u64 t; cvta.to.shared.u64 t, %1; cvt.u32.u64 %0, t; }" : "=r"(a) : "l"(p));
    return a;
}
__device__ __forceinline__ void cp16(uint32_t s, const void* g) {
    asm volatile("cp.async.cg.shared.global [%0], [%1], 16;\n" :: "r"(s), "l"(g));
}
__device__ __forceinline__ void cp_commit() { asm volatile("cp.async.commit_group;\n"); }
template<int N> __device__ __forceinline__ void cp_wait() {
    asm volatile("cp.async.wait_group %0;\n" :: "n"(N));
}
__device__ __forceinline__ void ldsm4(uint32_t& d0, uint32_t& d1, uint32_t& d2, uint32_t& d3,
                                      uint32_t a) {
    asm volatile("ldmatrix.sync.aligned.m8n8.x4.shared.b16 {%0,%1,%2,%3}, [%4];"
                 : "=r"(d0), "=r"(d1), "=r"(d2), "=r"(d3) : "r"(a));
}
__device__ __forceinline__ void mma16816(float& d0, float& d1, float& d2, float& d3,
                                         uint32_t a0, uint32_t a1, uint32_t a2, uint32_t a3,
                                         uint32_t b0, uint32_t b1) {
    asm volatile(
        "mma.sync.aligned.m16n8k16.row.col.f32.f16.f16.f32 "
        "{%0,%1,%2,%3}, {%4,%5,%6,%7}, {%8,%9}, {%0,%1,%2,%3};"
        : "+f"(d0), "+f"(d1), "+f"(d2), "+f"(d3)
        : "r"(a0), "r"(a1), "r"(a2), "r"(a3), "r"(b0), "r"(b1));
}

// ---------------------------------------------------------------------------
// conversion kernels (validated; rel_err 4.1e-4)
// ---------------------------------------------------------------------------
__global__ void cvt_x_kernel(const float* __restrict__ x0, const float* __restrict__ x1,
                             const float* __restrict__ x2)
{
    const size_t per = (size_t)BATCH * HDIM / 4;
    const size_t i = (size_t)blockIdx.x * blockDim.x + threadIdx.x;
    if (i >= 3 * per) return;
    const int bank = (int)(i / per);
    const size_t r = i - (size_t)bank * per;
    const float4 v = ((const float4*)(bank == 0 ? x0 : bank == 1 ? x1 : x2))[r];
    __half2 h0 = __floats2half2_rn(v.x, v.y);
    __half2 h1 = __floats2half2_rn(v.z, v.w);
    ((uint2*)g_Xh)[i] = make_uint2(*(uint32_t*)&h0, *(uint32_t*)&h1);
}

__global__ void cvt_w_kernel(const float* __restrict__ sW1, const float* __restrict__ tW1,
                             const float* __restrict__ sW2, const float* __restrict__ tW2)
{
    __shared__ float t[32][33];
    int b = blockIdx.x;
    const float* src; __half* dst; int N, n0, k0;
    if (b < NZ * 256) {
        const int z = b >> 8, r = b & 255;
        n0 = (r >> 4) * 32; k0 = (r & 15) * 32;
        src = (z < NEXP) ? sW1 + (size_t)z * HDIM * HDIM
                         : tW1 + (size_t)(z - NEXP) * HDIM * HDIM;
        dst = g_W1h + (size_t)z * HDIM * HDIM;
        N = HDIM;
    } else {
        b -= NZ * 256;
        const int z = b >> 6, r = b & 63;
        k0 = (r >> 2) * 32; n0 = (r & 3) * 32;
        src = (z < NEXP) ? sW2 + (size_t)z * HDIM * ODIM
                         : tW2 + (size_t)(z - NEXP) * HDIM * ODIM;
        dst = g_W2h + (size_t)z * ODIM * HDIM;
        N = ODIM;
    }
    const int tx = threadIdx.x, ty = threadIdx.y;
    #pragma unroll
    for (int i = 0; i < 4; ++i)
        t[ty + i * 8][tx] = src[(size_t)(k0 + ty + i * 8) * N + n0 + tx];
    __syncthreads();
    #pragma unroll
    for (int i = 0; i < 4; ++i)
        dst[(size_t)(n0 + ty + i * 8) * HDIM + k0 + tx] = __float2half_rn(t[tx][ty + i * 8]);
}

// ---------------------------------------------------------------------------
// gemm1: R10 config (unchanged) — BM=128 x BN1=128, 4 warps (warp 64x64)
// ---------------------------------------------------------------------------
__global__ __launch_bounds__(128, 2)
void gemm1_kernel(const float* __restrict__ sb1, const float* __restrict__ tb1)
{
    __shared__ __align__(1024) char smem[STAGES * STG1];   // 96 KB
    const uint32_t sb = smem_u32(smem);

    const int tid = threadIdx.x, lane = tid & 31, wid = tid >> 5;
    const int wm = wid >> 1, wn = wid & 1;
    const int bm = blockIdx.y * BM, bn = blockIdx.x * BN1;
    const int z = blockIdx.z, bank = z / NEXP, e = z - bank * NEXP;

    const __half* A = g_Xh + (size_t)bank * BATCH * HDIM;
    const __half* W = g_W1h + (size_t)z * HDIM * HDIM;
    const float* bias = (bank == 0) ? sb1 + (size_t)e * HDIM
                                    : tb1 + ((size_t)(bank - 1) * NEXP + e) * HDIM;
    __half* Hc = g_H + (size_t)z * BATCH * HDIM;

    const __half* Ag[8]; const __half* Bg[8]; uint32_t sAo[8], sBo[8];
    #pragma unroll
    for (int i = 0; i < 8; ++i) {
        const int idx = i * 128 + tid;
        const int r = idx >> 3, c = idx & 7;
        Ag[i] = A + (size_t)(bm + r) * HDIM + c * 8;
        Bg[i] = W + (size_t)(bn + r) * HDIM + c * 8;
        const uint32_t o = (uint32_t)(r * 128 + ((c ^ (r & 7)) << 4));
        sAo[i] = o;
        sBo[i] = B_OFF1 + o;
    }

    const int ah = lane >> 4;
    uint32_t art[4]; int arx[4];
    #pragma unroll
    for (int mi = 0; mi < 4; ++mi) {
        const int r = wm * 64 + mi * 16 + (lane & 15);
        art[mi] = (uint32_t)(r * 128); arx[mi] = r & 7;
    }
    const int bh = (lane >> 3) & 1;
    uint32_t nrt[4]; int nrx[4];
    #pragma unroll
    for (int p = 0; p < 4; ++p) {
        const int r = wn * 64 + p * 16 + ((lane >> 4) << 3) + (lane & 7);
        nrt[p] = B_OFF1 + (uint32_t)(r * 128); nrx[p] = r & 7;
    }

    float acc[4][8][4] = {};

    #pragma unroll
    for (int s = 0; s < STAGES - 1; ++s) {
        const int ko = s * BK;
        const uint32_t base = sb + s * STG1;
        #pragma unroll
        for (int i = 0; i < 8; ++i) { cp16(base + sAo[i], Ag[i] + ko); }
        #pragma unroll
        for (int i = 0; i < 8; ++i) { cp16(base + sBo[i], Bg[i] + ko); }
        cp_commit();
    }

    #pragma unroll 1
    for (int kt = 0; kt < NKT; ++kt) {
        cp_wait<STAGES - 2>();
        __syncthreads();

        if (kt + STAGES - 1 < NKT) {
            const int ko = (kt + STAGES - 1) * BK;
            const uint32_t base = sb + ((kt + STAGES - 1) % STAGES) * STG1;
            #pragma unroll
            for (int i = 0; i < 8; ++i) { cp16(base + sAo[i], Ag[i] + ko); }
            #pragma unroll
            for (int i = 0; i < 8; ++i) { cp16(base + sBo[i], Bg[i] + ko); }
        }
        cp_commit();

        const uint32_t stg = sb + (kt % STAGES) * STG1;
        #pragma unroll
        for (int k16 = 0; k16 < 4; ++k16) {
            const int ga = k16 * 2 + ah;
            const int gb = k16 * 2 + bh;
            uint32_t af[4][4], bf[8][2];
            #pragma unroll
            for (int mi = 0; mi < 4; ++mi)
                ldsm4(af[mi][0], af[mi][1], af[mi][2], af[mi][3],
                      stg + art[mi] + ((uint32_t)(ga ^ arx[mi]) << 4));
            #pragma unroll
            for (int p = 0; p < 4; ++p)
                ldsm4(bf[2 * p][0], bf[2 * p][1], bf[2 * p + 1][0], bf[2 * p + 1][1],
                      stg + nrt[p] + ((uint32_t)(gb ^ nrx[p]) << 4));
            #pragma unroll
            for (int mi = 0; mi < 4; ++mi)
                #pragma unroll
                for (int ni = 0; ni < 8; ++ni)
                    mma16816(acc[mi][ni][0], acc[mi][ni][1], acc[mi][ni][2], acc[mi][ni][3],
                             af[mi][0], af[mi][1], af[mi][2], af[mi][3],
                             bf[ni][0], bf[ni][1]);
        }
    }

    const int g = lane >> 2, t = lane & 3;
    #pragma unroll
    for (int mi = 0; mi < 4; ++mi) {
        const int r0g = bm + wm * 64 + mi * 16 + g;
        const int r1g = r0g + 8;
        #pragma unroll
        for (int ni = 0; ni < 8; ++ni) {
            const int c0g = bn + wn * 64 + ni * 8 + t * 2;
            const float bv0 = bias[c0g], bv1 = bias[c0g + 1];
            const float v00 = fmaxf(acc[mi][ni][0] + bv0, 0.0f);
            const float v01 = fmaxf(acc[mi][ni][1] + bv1, 0.0f);
            const float v10 = fmaxf(acc[mi][ni][2] + bv0, 0.0f);
            const float v11 = fmaxf(acc[mi][ni][3] + bv1, 0.0f);
            *(__half2*)&Hc[(size_t)r0g * HDIM + c0g] = __floats2half2_rn(v00, v01);
            *(__half2*)&Hc[(size_t)r1g * HDIM + c0g] = __floats2half2_rn(v10, v11);
        }
    }
}

// ---------------------------------------------------------------------------
// gemm2: NEW 12-warp/SM config — BM=128 x BN2=64, 4 warps (warp 64x32),
// 3 CTAs/SM (regs ~150 < 170 cap, no spill; smem 72KB x 3 = 216KB)
// ---------------------------------------------------------------------------
__global__ __launch_bounds__(128, 3)
void gemm2_kernel(const float* __restrict__ sb2, const float* __restrict__ tb2,
                  float* __restrict__ out)
{
    __shared__ __align__(1024) char smem[STAGES * STG2];   // 72 KB
    const uint32_t sb = smem_u32(smem);

    const int tid = threadIdx.x, lane = tid & 31, wid = tid >> 5;
    const int wm = wid >> 1, wn = wid & 1;                  // warps 2m x 2n, tile 64x32
    const int bm = blockIdx.y * BM, bn = blockIdx.x * BN2;
    const int z = blockIdx.z, bank = z / NEXP, e = z - bank * NEXP;

    const __half* A = g_H + (size_t)z * BATCH * HDIM;
    const __half* W = g_W2h + (size_t)z * ODIM * HDIM;
    const float* bias = (bank == 0) ? sb2 + (size_t)e * ODIM
                                    : tb2 + ((size_t)(bank - 1) * NEXP + e) * ODIM;
    float* Cb = out + (size_t)z * BATCH * ODIM;

    // cp.async mapping: A 8 granules/thread, B 4 granules/thread
    const __half* Ag[8]; uint32_t sAo[8];
    #pragma unroll
    for (int i = 0; i < 8; ++i) {
        const int idx = i * 128 + tid;
        const int r = idx >> 3, c = idx & 7;
        Ag[i] = A + (size_t)(bm + r) * HDIM + c * 8;
        sAo[i] = (uint32_t)(r * 128 + ((c ^ (r & 7)) << 4));
    }
    const __half* Bg[4]; uint32_t sBo[4];
    #pragma unroll
    for (int i = 0; i < 4; ++i) {
        const int idx = i * 128 + tid;
        const int r = idx >> 3, c = idx & 7;
        Bg[i] = W + (size_t)(bn + r) * HDIM + c * 8;
        sBo[i] = (uint32_t)(B_OFF2 + r * 128 + ((c ^ (r & 7)) << 4));
    }

    const int ah = lane >> 4;
    uint32_t art[4]; int arx[4];
    #pragma unroll
    for (int mi = 0; mi < 4; ++mi) {
        const int r = wm * 64 + mi * 16 + (lane & 15);
        art[mi] = (uint32_t)(r * 128); arx[mi] = r & 7;
    }
    const int bh = (lane >> 3) & 1;
    uint32_t nrt[2]; int nrx[2];
    #pragma unroll
    for (int p = 0; p < 2; ++p) {
        const int r = wn * 32 + p * 16 + ((lane >> 4) << 3) + (lane & 7);
        nrt[p] = (uint32_t)(B_OFF2 + r * 128); nrx[p] = r & 7;
    }

    float acc[4][4][4] = {};

    #pragma unroll
    for (int s = 0; s < STAGES - 1; ++s) {
        const int ko = s * BK;
        const uint32_t base = sb + s * STG2;
        #pragma unroll
        for (int i = 0; i < 8; ++i) { cp16(base + sAo[i], Ag[i] + ko); }
        #pragma unroll
        for (int i = 0; i < 4; ++i) { cp16(base + sBo[i], Bg[i] + ko); }
        cp_commit();
    }

    #pragma unroll 1
    for (int kt = 0; kt < NKT; ++kt) {
        cp_wait<STAGES - 2>();
        __syncthreads();

        if (kt + STAGES - 1 < NKT) {
            const int ko = (kt + STAGES - 1) * BK;
            const uint32_t base = sb + ((kt + STAGES - 1) % STAGES) * STG2;
            #pragma unroll
            for (int i = 0; i < 8; ++i) { cp16(base + sAo[i], Ag[i] + ko); }
            #pragma unroll
            for (int i = 0; i < 4; ++i) { cp16(base + sBo[i], Bg[i] + ko); }
        }
        cp_commit();

        const uint32_t stg = sb + (kt % STAGES) * STG2;
        #pragma unroll
        for (int k16 = 0; k16 < 4; ++k16) {
            const int ga = k16 * 2 + ah;
            const int gb = k16 * 2 + bh;
            uint32_t af[4][4], bf[4][2];
            #pragma unroll
            for (int mi = 0; mi < 4; ++mi)
                ldsm4(af[mi][0], af[mi][1], af[mi][2], af[mi][3],
                      stg + art[mi] + ((uint32_t)(ga ^ arx[mi]) << 4));
            #pragma unroll
            for (int p = 0; p < 2; ++p)
                ldsm4(bf[2 * p][0], bf[2 * p][1], bf[2 * p + 1][0], bf[2 * p + 1][1],
                      stg + nrt[p] + ((uint32_t)(gb ^ nrx[p]) << 4));
            #pragma unroll
            for (int mi = 0; mi < 4; ++mi)
                #pragma unroll
                for (int ni = 0; ni < 4; ++ni)
                    mma16816(acc[mi][ni][0], acc[mi][ni][1], acc[mi][ni][2], acc[mi][ni][3],
                             af[mi][0], af[mi][1], af[mi][2], af[mi][3],
                             bf[ni][0], bf[ni][1]);
        }
    }

    const int g = lane >> 2, t = lane & 3;
    #pragma unroll
    for (int mi = 0; mi < 4; ++mi) {
        const int r0g = bm + wm * 64 + mi * 16 + g;
        const int r1g = r0g + 8;
        #pragma unroll
        for (int ni = 0; ni < 4; ++ni) {
            const int c0g = bn + wn * 32 + ni * 8 + t * 2;
            const float bv0 = bias[c0g], bv1 = bias[c0g + 1];
            *(float2*)&Cb[(size_t)r0g * ODIM + c0g] =
                make_float2(acc[mi][ni][0] + bv0, acc[mi][ni][1] + bv1);
            *(float2*)&Cb[(size_t)r1g * ODIM + c0g] =
                make_float2(acc[mi][ni][2] + bv0, acc[mi][ni][3] + bv1);
        }
    }
}

// ---------------------------------------------------------------------------
// launch
// ---------------------------------------------------------------------------
extern "C" void kernel_launch(void* const* d_in, const int* in_sizes, int n_in,
                              void* d_out, int out_size)
{
    const float* share_x  = (const float*)d_in[0];
    const float* task_x0  = (const float*)d_in[1];
    const float* task_x1  = (const float*)d_in[2];
    const float* share_W1 = (const float*)d_in[3];
    const float* share_b1 = (const float*)d_in[4];
    const float* share_W2 = (const float*)d_in[5];
    const float* share_b2 = (const float*)d_in[6];
    const float* task_W1  = (const float*)d_in[7];
    const float* task_b1  = (const float*)d_in[8];
    const float* task_W2  = (const float*)d_in[9];
    const float* task_b2  = (const float*)d_in[10];
    float* out = (float*)d_out;

    const size_t nx4 = (size_t)3 * BATCH * HDIM / 4;
    cvt_x_kernel<<<(unsigned)((nx4 + 255) / 256), 256>>>(share_x, task_x0, task_x1);
    cvt_w_kernel<<<NZ * 256 + NZ * 64, dim3(32, 8)>>>(share_W1, task_W1, share_W2, task_W2);

    gemm1_kernel<<<dim3(HDIM / BN1, BATCH / BM, NZ), 128>>>(share_b1, task_b1);
    gemm2_kernel<<<dim3(ODIM / BN2, BATCH / BM, NZ), 128>>>(share_b2, task_b2, out);
}